// round 14
// baseline (speedup 1.0000x reference)
#include <cuda_runtime.h>

#define NPTS  1024
#define BTOT  32
#define RESV  48
#define SPIX  (RESV*RESV)

#define NPB   3              // blocks per batch
#define NSUBL 8              // 2-row sub-strips per block (16 rows)
#define NCB   8              // col bins (6 cols each)
#define NBINL 64             // bins per block
#define SCAP  6592           // packed capacity: 6*1024 + 64*7 pad (proven bound)
#define SPAD  (SCAP+8)

// dynamic smem layout (bytes)
#define OFF_SBIN  0                        // float4 sbin[SPAD]      105600
#define OFF_WBASE 105600                   // int wbase[64][32]        8192
#define OFF_BALS  113792                   // uint balS[32][8]         1024
#define OFF_BALC  114816                   // uint balC[32][8]         1024
#define OFF_PBASE 115840                   // int pbase[64]             256
#define OFF_SCNT  116096                   // int scnt[64]              256
#define OFF_RED   116352                   // float red[128]            512
#define SMEMB     116864

extern __shared__ char smem_raw[];

__device__ __forceinline__ bool sub_cond(float X, int s) {
    // sub-strip s covers rows 2s, 2s+1; reachable iff X in (2s-2, 2s+3)
    return (X > (float)(2 * s) - 2.0f) && (X < (float)(2 * s) + 3.0f);
}
__device__ __forceinline__ bool col_cond(float Y, int c) {
    return (Y > (float)(6 * c) - 2.0f) && (Y < (float)(6 * c + 5) + 2.0f);
}

// ---------------------------------------------------------------------------
// Single fused kernel: 96 blocks x 1024 threads.
// Block b3: batch b = b3/3, third h = b3%3 (rows 16h .. 16h+15).
// ---------------------------------------------------------------------------
__global__ void __launch_bounds__(1024)
p2m_kernel(const float* __restrict__ xyz,
           const float* __restrict__ feats,
           const float* __restrict__ theta,
           const float* __restrict__ phi,
           float* __restrict__ out)
{
    float4*   sbin  = (float4*)(smem_raw + OFF_SBIN);
    int*      wbase = (int*)(smem_raw + OFF_WBASE);
    unsigned* balS  = (unsigned*)(smem_raw + OFF_BALS);
    unsigned* balC  = (unsigned*)(smem_raw + OFF_BALC);
    int*      pbase = (int*)(smem_raw + OFF_PBASE);
    int*      scnt  = (int*)(smem_raw + OFF_SCNT);
    float*    red   = (float*)(smem_raw + OFF_RED);

    int b3 = blockIdx.x;
    int b = b3 / 3, h = b3 - 3 * b;
    int k = b >> 2, m = b & 3;
    int sbase0 = NSUBL * h;                 // first substrip of this block
    int tid = threadIdx.x, lane = tid & 31, wid = tid >> 5;

    // ---- Phase A: projection + top-2 features (1 point/thread) ----
    float th = theta[m], ph = phi[m];
    float st = sinf(th), ct = cosf(th);
    float sp = sinf(ph), cp = cosf(ph);
    float U0 = -st, U1 = ct;
    float V0 = ct * sp, V1 = st * sp, V2 = cp;
    float cx = ct * cp, cy = st * cp, cz = sp;

    int g = k * NPTS + tid;
    float x = xyz[3 * g + 0];
    float y = xyz[3 * g + 1];
    float z = xyz[3 * g + 2];
    float dx = x - cx, dy = y - cy, dz = z - cz;
    float c0 = dx * U0 + dy * U1;
    float c1 = dx * V0 + dy * V1 + dz * V2;

    // top-2 of 20 with two independent chains (2x ILP), exact merge.
    const float4* fr = (const float4*)(feats + (size_t)g * 20);
    float p1 = -1e30f, p2 = -1e30f;
    float q1 = -1e30f, q2 = -1e30f;
#pragma unroll
    for (int q = 0; q < 5; q++) {
        float4 v = fr[q];
        float f;
        f = v.x; if (f > p1) { p2 = p1; p1 = f; } else if (f > p2) p2 = f;
        f = v.y; if (f > q1) { q2 = q1; q1 = f; } else if (f > q2) q2 = f;
        f = v.z; if (f > p1) { p2 = p1; p1 = f; } else if (f > p2) p2 = f;
        f = v.w; if (f > q1) { q2 = q1; q1 = f; } else if (f > q2) q2 = f;
    }
    float t1 = fmaxf(p1, q1);
    float t2 = fmaxf(fminf(p1, q1), fmaxf(p2, q2));

    // ---- Phase B: exact block minmax (hierarchical: warp -> warp0) ----
    float mn0 = c0, mx0 = c0, mn1 = c1, mx1 = c1;
#pragma unroll
    for (int o = 16; o > 0; o >>= 1) {
        mn0 = fminf(mn0, __shfl_xor_sync(0xffffffffu, mn0, o));
        mx0 = fmaxf(mx0, __shfl_xor_sync(0xffffffffu, mx0, o));
        mn1 = fminf(mn1, __shfl_xor_sync(0xffffffffu, mn1, o));
        mx1 = fmaxf(mx1, __shfl_xor_sync(0xffffffffu, mx1, o));
    }
    if (lane == 0) {
        red[wid] = mn0; red[32 + wid] = mx0;
        red[64 + wid] = mn1; red[96 + wid] = mx1;
    }
    __syncthreads();
    if (wid == 0) {
        float a = red[lane], bmx = red[32 + lane];
        float cmn = red[64 + lane], dmx = red[96 + lane];
#pragma unroll
        for (int o = 16; o > 0; o >>= 1) {
            a   = fminf(a,   __shfl_xor_sync(0xffffffffu, a,   o));
            bmx = fmaxf(bmx, __shfl_xor_sync(0xffffffffu, bmx, o));
            cmn = fminf(cmn, __shfl_xor_sync(0xffffffffu, cmn, o));
            dmx = fmaxf(dmx, __shfl_xor_sync(0xffffffffu, dmx, o));
        }
        if (lane == 0) { red[0] = a; red[32] = bmx; red[64] = cmn; red[96] = dmx; }
    }
    __syncthreads();
    mn0 = red[0]; mx0 = red[32]; mn1 = red[64]; mx1 = red[96];

    float ctr0 = (mx0 + mn0) * 0.5f;
    float ctr1 = (mx1 + mn1) * 0.5f;
    float sc0  = fmaxf(mx0 - mn0, 1e-5f) * 0.5f;
    float sc1  = fmaxf(mx1 - mn1, 1e-5f) * 0.5f;

    float X = (__fdiv_rn(c0 - ctr0, sc0) + 1.0f) * 19.2f + 4.8f;
    float Y = (__fdiv_rn(c1 - ctr1, sc1) + 1.0f) * 19.2f + 4.8f;

    // ---- Phase C: factored ballots (8 substrips + 8 cols per warp) ----
#pragma unroll
    for (int sl = 0; sl < NSUBL; sl++) {
        unsigned ba = __ballot_sync(0xffffffffu, sub_cond(X, sbase0 + sl));
        if (lane == 0) balS[wid * NSUBL + sl] = ba;
    }
#pragma unroll
    for (int c = 0; c < NCB; c++) {
        unsigned ba = __ballot_sync(0xffffffffu, col_cond(Y, c));
        if (lane == 0) balC[wid * NCB + c] = ba;
    }
    __syncthreads();

    // ---- Phase D: 64 per-bin cross-warp scans (warp w: bins 2w, 2w+1) ----
#pragma unroll
    for (int e = 0; e < 2; e++) {
        int bin = wid * 2 + e;
        int sl = bin >> 3, c = bin & 7;
        int v = __popc(balS[lane * NSUBL + sl] & balC[lane * NCB + c]);
        int incl = v;
#pragma unroll
        for (int o = 1; o < 32; o <<= 1) {
            int n = __shfl_up_sync(0xffffffffu, incl, o);
            if (lane >= o) incl += n;
        }
        wbase[bin * 32 + lane] = incl - v;
        if (lane == 31) pbase[bin] = incl;    // bin total (temp)
    }
    __syncthreads();

    // ---- Phase E: packed-offset scan over 64 bins (warp 0, pad to 8) ----
    if (wid == 0) {
        int carry = 0;
#pragma unroll
        for (int rr = 0; rr < 2; rr++) {
            int lb  = rr * 32 + lane;
            int tot = pbase[lb];
            int pad8 = (tot + 7) & ~7;
            int incl = pad8;
#pragma unroll
            for (int o = 1; o < 32; o <<= 1) {
                int n = __shfl_up_sync(0xffffffffu, incl, o);
                if (lane >= o) incl += n;
            }
            int base = carry + incl - pad8;
            scnt[lb]  = min(tot, max(0, SCAP - base));   // clamp provably never fires
            pbase[lb] = base;
            carry += __shfl_sync(0xffffffffu, incl, 31);
        }
    }
    __syncthreads();

    // ---- Phase F: ordered scatter + sentinel pad fill ----
    {
        unsigned lmask = (1u << lane) - 1u;
        float4 rec = make_float4(X, Y, t2, t1);
        int s0 = (int)floorf((X - 3.0f) * 0.5f);
        if (s0 < sbase0) s0 = sbase0;
        int cb0 = (int)floorf((Y - 7.0f) * (1.0f / 6.0f));
        if (cb0 < 0) cb0 = 0;
#pragma unroll
        for (int ds = 0; ds < 4; ds++) {
            int s = s0 + ds;
            if (s >= sbase0 + NSUBL || !sub_cond(X, s)) continue;
            int sl = s - sbase0;
            unsigned mS = balS[wid * NSUBL + sl];
#pragma unroll
            for (int dc = 0; dc < 3; dc++) {
                int c = cb0 + dc;
                if (c >= NCB || !col_cond(Y, c)) continue;
                unsigned ba = mS & balC[wid * NCB + c];
                int lb = sl * NCB + c;
                int rank = wbase[lb * 32 + wid] + __popc(ba & lmask);
                if (rank < scnt[lb]) sbin[pbase[lb] + rank] = rec;
            }
        }
        // sentinel pads: slots [tot, pad8) are never written by scatter
#pragma unroll
        for (int e = 0; e < 2; e++) {
            int lb = wid * 2 + e;
            int tb = scnt[lb];
            int npad = ((tb + 7) & ~7) - tb;
            if (lane < npad)
                sbin[pbase[lb] + tb + lane] = make_float4(-100.f, -100.f, 0.f, 0.f);
        }
    }
    __syncthreads();

    // ---- Phase G: per-pixel ball query. 24 warp-tasks, one per warp ----
    if (wid < 24) {
        int sl = wid / 3, cgrp = wid - 3 * sl;
        int r  = lane >> 4, ccol = lane & 15;
        int i  = 16 * h + 2 * sl + r;
        int j  = 16 * cgrp + ccol;
        int c  = j / 6;
        int lb = sl * NCB + c;
        int tot = scnt[lb];
        int pad8 = (tot + 7) & ~7;
        const float4* bp = sbin + pbase[lb];

        int pmax = pad8;
#pragma unroll
        for (int o = 16; o > 0; o >>= 1)
            pmax = max(pmax, __shfl_xor_sync(0xffffffffu, pmax, o));

        float sx = (float)i, sy = (float)j;
        int nsel = 0;
        float f0 = 0.0f, f1 = 0.0f;

        for (int p0 = 0; p0 < pmax; p0 += 8) {
            // unconditional LDS.128 (full MLP); reads stay inside sbin[SPAD]
            float4 q0 = bp[p0 + 0], q1v = bp[p0 + 1], q2v = bp[p0 + 2], q3 = bp[p0 + 3];
            float4 q4 = bp[p0 + 4], q5 = bp[p0 + 5], q6 = bp[p0 + 6], q7 = bp[p0 + 7];
            float d0, d1, d2v, d3, d4, d5, d6, d7;
            { float a = sx - q0.x,  bb = sy - q0.y;  d0  = fmaf(a, a, bb * bb); }
            { float a = sx - q1v.x, bb = sy - q1v.y; d1  = fmaf(a, a, bb * bb); }
            { float a = sx - q2v.x, bb = sy - q2v.y; d2v = fmaf(a, a, bb * bb); }
            { float a = sx - q3.x,  bb = sy - q3.y;  d3  = fmaf(a, a, bb * bb); }
            { float a = sx - q4.x,  bb = sy - q4.y;  d4  = fmaf(a, a, bb * bb); }
            { float a = sx - q5.x,  bb = sy - q5.y;  d5  = fmaf(a, a, bb * bb); }
            { float a = sx - q6.x,  bb = sy - q6.y;  d6  = fmaf(a, a, bb * bb); }
            { float a = sx - q7.x,  bb = sy - q7.y;  d7  = fmaf(a, a, bb * bb); }

            // independent hit flags (chunks past this lane's pad8 contribute 0;
            // sentinel pads in [tot,pad8) have d2 ~ 1.2e4, never hit)
            bool ok = p0 < pad8;
            int h0 = ok & (d0  < 4.0f); int h1 = ok & (d1  < 4.0f);
            int h2 = ok & (d2v < 4.0f); int h3 = ok & (d3  < 4.0f);
            int h4 = ok & (d4  < 4.0f); int h5 = ok & (d5  < 4.0f);
            int h6 = ok & (d6  < 4.0f); int h7 = ok & (d7  < 4.0f);
            int cnt = ((h0 + h1) + (h2 + h3)) + ((h4 + h5) + (h6 + h7));

            // fast path: all hits fit under the 16 cap -> take all (tree sums)
            if (__all_sync(0xffffffffu, nsel + cnt <= 16)) {
                float s0z = (h0 ? q0.z  : 0.f) + (h1 ? q1v.z : 0.f);
                float s1z = (h2 ? q2v.z : 0.f) + (h3 ? q3.z  : 0.f);
                float s2z = (h4 ? q4.z  : 0.f) + (h5 ? q5.z  : 0.f);
                float s3z = (h6 ? q6.z  : 0.f) + (h7 ? q7.z  : 0.f);
                f0 += (s0z + s1z) + (s2z + s3z);
                float s0w = (h0 ? q0.w  : 0.f) + (h1 ? q1v.w : 0.f);
                float s1w = (h2 ? q2v.w : 0.f) + (h3 ? q3.w  : 0.f);
                float s2w = (h4 ? q4.w  : 0.f) + (h5 ? q5.w  : 0.f);
                float s3w = (h6 ? q6.w  : 0.f) + (h7 ? q7.w  : 0.f);
                f1 += (s0w + s1w) + (s2w + s3w);
                nsel += cnt;
            } else {
                // exact serial fallback (cap-crossing chunk, rare)
                if (h0 && nsel < 16) { f0 += q0.z;  f1 += q0.w;  nsel++; }
                if (h1 && nsel < 16) { f0 += q1v.z; f1 += q1v.w; nsel++; }
                if (h2 && nsel < 16) { f0 += q2v.z; f1 += q2v.w; nsel++; }
                if (h3 && nsel < 16) { f0 += q3.z;  f1 += q3.w;  nsel++; }
                if (h4 && nsel < 16) { f0 += q4.z;  f1 += q4.w;  nsel++; }
                if (h5 && nsel < 16) { f0 += q5.z;  f1 += q5.w;  nsel++; }
                if (h6 && nsel < 16) { f0 += q6.z;  f1 += q6.w;  nsel++; }
                if (h7 && nsel < 16) { f0 += q7.z;  f1 += q7.w;  nsel++; }
            }
            if (__all_sync(0xffffffffu, (p0 + 8 >= pad8) | (nsel >= 16))) break;
        }

        float occ = fmaxf((float)nsel, 1.0f);
        float a0 = __fdiv_rn(f0, occ);
        float a1 = __fdiv_rn(f1, occ);
        float mxv = fmaxf(a0, a1);
        float e0 = expf(a0 - mxv);
        float e1 = expf(a1 - mxv);
        float ssum = e0 + e1;
        float nf0 = __fdiv_rn(e0, ssum);
        float nf1 = __fdiv_rn(e1, ssum);
        float v = (nf0 == nf1) ? 0.0f : nf1 * 255.0f;

        int base = (b * 3) * SPIX + i * RESV + j;
        out[base]            = v;
        out[base + SPIX]     = v;
        out[base + 2 * SPIX] = v;
    }
}

extern "C" void kernel_launch(void* const* d_in, const int* in_sizes, int n_in,
                              void* d_out, int out_size)
{
    const float* xyz   = (const float*)d_in[0];
    const float* feats = (const float*)d_in[1];
    const float* theta = (const float*)d_in[n_in - 2];
    const float* phi   = (const float*)d_in[n_in - 1];
    float* out = (float*)d_out;

    cudaFuncSetAttribute(p2m_kernel,
                         cudaFuncAttributeMaxDynamicSharedMemorySize, SMEMB);
    p2m_kernel<<<BTOT * NPB, 1024, SMEMB>>>(xyz, feats, theta, phi, out);
}

// round 16
// speedup vs baseline: 1.0976x; 1.0976x over previous
#include <cuda_runtime.h>

#define NPTS  1024
#define BTOT  32
#define RESV  48
#define SPIX  (RESV*RESV)

#define QPB   4              // mask blocks per batch (12 rows each)
#define NSUBL 6              // 2-row sub-strips per mask block
#define NCB   8              // col bins (6 cols each)
#define NBINL 48             // bins per mask block
#define SCAP  6480           // 6 copies/pt * 1024 + 48*7 pad (proven bound)
#define SPAD  (SCAP+8)

// mask-kernel dynamic smem layout (bytes)
#define OFF_SBIN  0                        // float4 sbin[SPAD]       103808
#define OFF_WBASE 103808                   // int wbase[48][32]         6144
#define OFF_BALS  109952                   // uint balS[32][6]           768
#define OFF_BALC  110720                   // uint balC[32][8]          1024
#define OFF_PBASE 111744                   // int pbase[48]              192
#define OFF_SCNT  111936                   // int scnt[48]               192
#define SMEMB     112128

// global handoff: one record (X, Y, f_second, f_max) per (batch, point)
__device__ float4 g_rec[BTOT * NPTS];

extern __shared__ char smem_raw[];

__device__ __forceinline__ bool sub_cond(float X, int s) {
    // sub-strip s covers rows 2s, 2s+1; reachable iff X in (2s-2, 2s+3)
    return (X > (float)(2 * s) - 2.0f) && (X < (float)(2 * s) + 3.0f);
}
__device__ __forceinline__ bool col_cond(float Y, int c) {
    return (Y > (float)(6 * c) - 2.0f) && (Y < (float)(6 * c + 5) + 2.0f);
}

// ---------------------------------------------------------------------------
// Kernel 1 (light prep): 32 blocks x 1024 threads, 1 point/thread.
// project + top-2 + exact minmax + normalize -> coalesced record write.
// ---------------------------------------------------------------------------
__global__ void __launch_bounds__(1024)
prep_kernel(const float* __restrict__ xyz,
            const float* __restrict__ feats,
            const float* __restrict__ theta,
            const float* __restrict__ phi)
{
    __shared__ float red[128];

    int b = blockIdx.x;
    int k = b >> 2, m = b & 3;
    int tid = threadIdx.x, lane = tid & 31, wid = tid >> 5;

    float th = theta[m], ph = phi[m];
    float st = sinf(th), ct = cosf(th);
    float sp = sinf(ph), cp = cosf(ph);
    float U0 = -st, U1 = ct;
    float V0 = ct * sp, V1 = st * sp, V2 = cp;
    float cx = ct * cp, cy = st * cp, cz = sp;

    int g = k * NPTS + tid;
    float x = xyz[3 * g + 0];
    float y = xyz[3 * g + 1];
    float z = xyz[3 * g + 2];
    float dx = x - cx, dy = y - cy, dz = z - cz;
    float c0 = dx * U0 + dy * U1;
    float c1 = dx * V0 + dy * V1 + dz * V2;

    // top-2 of 20, two independent chains (2x ILP), exact merge
    const float4* fr = (const float4*)(feats + (size_t)g * 20);
    float p1 = -1e30f, p2 = -1e30f, q1 = -1e30f, q2 = -1e30f;
#pragma unroll
    for (int q = 0; q < 5; q++) {
        float4 v = fr[q];
        float f;
        f = v.x; if (f > p1) { p2 = p1; p1 = f; } else if (f > p2) p2 = f;
        f = v.y; if (f > q1) { q2 = q1; q1 = f; } else if (f > q2) q2 = f;
        f = v.z; if (f > p1) { p2 = p1; p1 = f; } else if (f > p2) p2 = f;
        f = v.w; if (f > q1) { q2 = q1; q1 = f; } else if (f > q2) q2 = f;
    }
    float t1 = fmaxf(p1, q1);
    float t2 = fmaxf(fminf(p1, q1), fmaxf(p2, q2));

    // exact hierarchical minmax
    float mn0 = c0, mx0 = c0, mn1 = c1, mx1 = c1;
#pragma unroll
    for (int o = 16; o > 0; o >>= 1) {
        mn0 = fminf(mn0, __shfl_xor_sync(0xffffffffu, mn0, o));
        mx0 = fmaxf(mx0, __shfl_xor_sync(0xffffffffu, mx0, o));
        mn1 = fminf(mn1, __shfl_xor_sync(0xffffffffu, mn1, o));
        mx1 = fmaxf(mx1, __shfl_xor_sync(0xffffffffu, mx1, o));
    }
    if (lane == 0) {
        red[wid] = mn0; red[32 + wid] = mx0;
        red[64 + wid] = mn1; red[96 + wid] = mx1;
    }
    __syncthreads();
    if (wid == 0) {
        float a = red[lane], bmx = red[32 + lane];
        float cmn = red[64 + lane], dmx = red[96 + lane];
#pragma unroll
        for (int o = 16; o > 0; o >>= 1) {
            a   = fminf(a,   __shfl_xor_sync(0xffffffffu, a,   o));
            bmx = fmaxf(bmx, __shfl_xor_sync(0xffffffffu, bmx, o));
            cmn = fminf(cmn, __shfl_xor_sync(0xffffffffu, cmn, o));
            dmx = fmaxf(dmx, __shfl_xor_sync(0xffffffffu, dmx, o));
        }
        if (lane == 0) { red[0] = a; red[32] = bmx; red[64] = cmn; red[96] = dmx; }
    }
    __syncthreads();
    mn0 = red[0]; mx0 = red[32]; mn1 = red[64]; mx1 = red[96];

    float ctr0 = (mx0 + mn0) * 0.5f;
    float ctr1 = (mx1 + mn1) * 0.5f;
    float sc0  = fmaxf(mx0 - mn0, 1e-5f) * 0.5f;
    float sc1  = fmaxf(mx1 - mn1, 1e-5f) * 0.5f;

    float X = (__fdiv_rn(c0 - ctr0, sc0) + 1.0f) * 19.2f + 4.8f;
    float Y = (__fdiv_rn(c1 - ctr1, sc1) + 1.0f) * 19.2f + 4.8f;

    g_rec[b * NPTS + tid] = make_float4(X, Y, t2, t1);   // coalesced STG.128
}

// ---------------------------------------------------------------------------
// Kernel 2 (mask): 128 blocks x 1024 threads.
// Block: batch b = blk>>2, quarter q = blk&3 (rows 12q .. 12q+11).
// ---------------------------------------------------------------------------
__global__ void __launch_bounds__(1024)
mask_kernel(float* __restrict__ out)
{
    float4*   sbin  = (float4*)(smem_raw + OFF_SBIN);
    int*      wbase = (int*)(smem_raw + OFF_WBASE);
    unsigned* balS  = (unsigned*)(smem_raw + OFF_BALS);
    unsigned* balC  = (unsigned*)(smem_raw + OFF_BALC);
    int*      pbase = (int*)(smem_raw + OFF_PBASE);
    int*      scnt  = (int*)(smem_raw + OFF_SCNT);

    int blk = blockIdx.x;
    int b = blk >> 2, qh = blk & 3;
    int sbase0 = NSUBL * qh;                 // first substrip (global index)
    int tid = threadIdx.x, lane = tid & 31, wid = tid >> 5;

    // one record per thread, index-ordered (warp-major = index order)
    float4 rec = g_rec[b * NPTS + tid];
    float X = rec.x, Y = rec.y;

    // ---- ballots: 6 substrips + 8 cols per warp ----
#pragma unroll
    for (int sl = 0; sl < NSUBL; sl++) {
        unsigned ba = __ballot_sync(0xffffffffu, sub_cond(X, sbase0 + sl));
        if (lane == 0) balS[wid * NSUBL + sl] = ba;
    }
#pragma unroll
    for (int c = 0; c < NCB; c++) {
        unsigned ba = __ballot_sync(0xffffffffu, col_cond(Y, c));
        if (lane == 0) balC[wid * NCB + c] = ba;
    }
    __syncthreads();

    // ---- 48 per-bin cross-warp scans (warps 0..23 take 2 bins each) ----
    if (wid < 24) {
#pragma unroll
        for (int e = 0; e < 2; e++) {
            int bin = wid * 2 + e;
            int sl = bin >> 3, c = bin & 7;
            int v = __popc(balS[lane * NSUBL + sl] & balC[lane * NCB + c]);
            int incl = v;
#pragma unroll
            for (int o = 1; o < 32; o <<= 1) {
                int n = __shfl_up_sync(0xffffffffu, incl, o);
                if (lane >= o) incl += n;
            }
            wbase[bin * 32 + lane] = incl - v;
            if (lane == 31) pbase[bin] = incl;     // bin total (temp)
        }
    }
    __syncthreads();

    // ---- packed-offset scan over 48 bins (warp 0, pad to 8) ----
    if (wid == 0) {
        int carry = 0;
#pragma unroll
        for (int rr = 0; rr < 2; rr++) {
            int lb = rr * 32 + lane;
            int tot = (lb < NBINL) ? pbase[lb] : 0;
            int pad8 = (tot + 7) & ~7;
            int incl = pad8;
#pragma unroll
            for (int o = 1; o < 32; o <<= 1) {
                int n = __shfl_up_sync(0xffffffffu, incl, o);
                if (lane >= o) incl += n;
            }
            int base = carry + incl - pad8;
            if (lb < NBINL) {
                scnt[lb]  = min(tot, max(0, SCAP - base));  // provably no clamp
                pbase[lb] = base;
            }
            carry += __shfl_sync(0xffffffffu, incl, 31);
        }
    }
    __syncthreads();

    // ---- ordered scatter (<=6 copies/point) ----
    {
        unsigned lmask = (1u << lane) - 1u;
        int s0 = (int)floorf((X - 3.0f) * 0.5f);
        if (s0 < sbase0) s0 = sbase0;
        int cb0 = (int)floorf((Y - 7.0f) * (1.0f / 6.0f));
        if (cb0 < 0) cb0 = 0;
#pragma unroll
        for (int ds = 0; ds < 4; ds++) {
            int s = s0 + ds;
            if (s >= sbase0 + NSUBL || !sub_cond(X, s)) continue;
            int sl = s - sbase0;
            unsigned mS = balS[wid * NSUBL + sl];
#pragma unroll
            for (int dc = 0; dc < 3; dc++) {
                int c = cb0 + dc;
                if (c >= NCB || !col_cond(Y, c)) continue;
                unsigned ba = mS & balC[wid * NCB + c];
                int lb = sl * NCB + c;
                int rank = wbase[lb * 32 + wid] + __popc(ba & lmask);
                if (rank < scnt[lb]) sbin[pbase[lb] + rank] = rec;
            }
        }
    }
    __syncthreads();
    // pads (slots [tot, pad8) never written by scatter)
    if (wid < 24) {
#pragma unroll
        for (int e = 0; e < 2; e++) {
            int lb = wid * 2 + e;
            int tb = scnt[lb];
            int npad = ((tb + 7) & ~7) - tb;
            if (lane < npad)
                sbin[pbase[lb] + tb + lane] = make_float4(-100.f, -100.f, 0.f, 0.f);
        }
    }
    __syncthreads();

    // ---- per-pixel ball query: 18 warp-tasks (2 rows x 16 cols each) ----
    if (wid < 18) {
        int sl = wid / 3, cgrp = wid - 3 * sl;
        int r  = lane >> 4, ccol = lane & 15;
        int i  = 12 * qh + 2 * sl + r;
        int j  = 16 * cgrp + ccol;
        int c  = j / 6;
        int lb = sl * NCB + c;
        int tot = scnt[lb];
        int pad8 = (tot + 7) & ~7;
        const float4* bp = sbin + pbase[lb];

        int pmax = pad8;
#pragma unroll
        for (int o = 16; o > 0; o >>= 1)
            pmax = max(pmax, __shfl_xor_sync(0xffffffffu, pmax, o));

        float sx = (float)i, sy = (float)j;
        int nsel = 0;
        float f0 = 0.0f, f1 = 0.0f;

        for (int p0 = 0; p0 < pmax; p0 += 8) {
            float4 q0 = bp[p0 + 0], q1v = bp[p0 + 1], q2v = bp[p0 + 2], q3 = bp[p0 + 3];
            float4 q4 = bp[p0 + 4], q5 = bp[p0 + 5], q6 = bp[p0 + 6], q7 = bp[p0 + 7];
            float d0, d1, d2v, d3, d4, d5, d6, d7;
            { float a = sx - q0.x,  bb = sy - q0.y;  d0  = fmaf(a, a, bb * bb); }
            { float a = sx - q1v.x, bb = sy - q1v.y; d1  = fmaf(a, a, bb * bb); }
            { float a = sx - q2v.x, bb = sy - q2v.y; d2v = fmaf(a, a, bb * bb); }
            { float a = sx - q3.x,  bb = sy - q3.y;  d3  = fmaf(a, a, bb * bb); }
            { float a = sx - q4.x,  bb = sy - q4.y;  d4  = fmaf(a, a, bb * bb); }
            { float a = sx - q5.x,  bb = sy - q5.y;  d5  = fmaf(a, a, bb * bb); }
            { float a = sx - q6.x,  bb = sy - q6.y;  d6  = fmaf(a, a, bb * bb); }
            { float a = sx - q7.x,  bb = sy - q7.y;  d7  = fmaf(a, a, bb * bb); }

            bool ok = p0 < pad8;   // sentinel pads never hit (d2 ~ 1.2e4)
            int h0 = ok & (d0  < 4.0f); int h1 = ok & (d1  < 4.0f);
            int h2 = ok & (d2v < 4.0f); int h3 = ok & (d3  < 4.0f);
            int h4 = ok & (d4  < 4.0f); int h5 = ok & (d5  < 4.0f);
            int h6 = ok & (d6  < 4.0f); int h7 = ok & (d7  < 4.0f);
            int cnt = ((h0 + h1) + (h2 + h3)) + ((h4 + h5) + (h6 + h7));

            if (__all_sync(0xffffffffu, nsel + cnt <= 16)) {
                float s0z = (h0 ? q0.z  : 0.f) + (h1 ? q1v.z : 0.f);
                float s1z = (h2 ? q2v.z : 0.f) + (h3 ? q3.z  : 0.f);
                float s2z = (h4 ? q4.z  : 0.f) + (h5 ? q5.z  : 0.f);
                float s3z = (h6 ? q6.z  : 0.f) + (h7 ? q7.z  : 0.f);
                f0 += (s0z + s1z) + (s2z + s3z);
                float s0w = (h0 ? q0.w  : 0.f) + (h1 ? q1v.w : 0.f);
                float s1w = (h2 ? q2v.w : 0.f) + (h3 ? q3.w  : 0.f);
                float s2w = (h4 ? q4.w  : 0.f) + (h5 ? q5.w  : 0.f);
                float s3w = (h6 ? q6.w  : 0.f) + (h7 ? q7.w  : 0.f);
                f1 += (s0w + s1w) + (s2w + s3w);
                nsel += cnt;
            } else {
                if (h0 && nsel < 16) { f0 += q0.z;  f1 += q0.w;  nsel++; }
                if (h1 && nsel < 16) { f0 += q1v.z; f1 += q1v.w; nsel++; }
                if (h2 && nsel < 16) { f0 += q2v.z; f1 += q2v.w; nsel++; }
                if (h3 && nsel < 16) { f0 += q3.z;  f1 += q3.w;  nsel++; }
                if (h4 && nsel < 16) { f0 += q4.z;  f1 += q4.w;  nsel++; }
                if (h5 && nsel < 16) { f0 += q5.z;  f1 += q5.w;  nsel++; }
                if (h6 && nsel < 16) { f0 += q6.z;  f1 += q6.w;  nsel++; }
                if (h7 && nsel < 16) { f0 += q7.z;  f1 += q7.w;  nsel++; }
            }
            if (__all_sync(0xffffffffu, (p0 + 8 >= pad8) | (nsel >= 16))) break;
        }

        float occ = fmaxf((float)nsel, 1.0f);
        float a0 = __fdiv_rn(f0, occ);
        float a1 = __fdiv_rn(f1, occ);
        float mxv = fmaxf(a0, a1);
        float e0 = expf(a0 - mxv);
        float e1 = expf(a1 - mxv);
        float ssum = e0 + e1;
        float nf0 = __fdiv_rn(e0, ssum);
        float nf1 = __fdiv_rn(e1, ssum);
        float v = (nf0 == nf1) ? 0.0f : nf1 * 255.0f;

        int base = (b * 3) * SPIX + i * RESV + j;
        out[base]            = v;
        out[base + SPIX]     = v;
        out[base + 2 * SPIX] = v;
    }
}

extern "C" void kernel_launch(void* const* d_in, const int* in_sizes, int n_in,
                              void* d_out, int out_size)
{
    const float* xyz   = (const float*)d_in[0];
    const float* feats = (const float*)d_in[1];
    const float* theta = (const float*)d_in[n_in - 2];
    const float* phi   = (const float*)d_in[n_in - 1];
    float* out = (float*)d_out;

    cudaFuncSetAttribute(mask_kernel,
                         cudaFuncAttributeMaxDynamicSharedMemorySize, SMEMB);

    prep_kernel<<<BTOT, 1024>>>(xyz, feats, theta, phi);
    mask_kernel<<<BTOT * QPB, 1024, SMEMB>>>(out);
}